// round 14
// baseline (speedup 1.0000x reference)
#include <cuda_runtime.h>
#include <cuda_bf16.h>

// ---------------- problem constants ----------------
#define NB     4
#define TFRM   400
#define NHARM  100
#define LAUD   96000

// ---------------- static device scratch ----------------
__device__ float g_scan[NB * LAUD];   // inner0 prefixes, then final inclusive phase
__device__ float g_h[NB * 32 * TFRM]; // conv1 activations
__device__ float g_mix[NB * TFRM];    // sigmoid mix at frame rate

// ---------------- rounding-exact helpers (R3-best forms, all uncontracted) ----------------

// pos = clip((l+0.5)*(T/L) - 0.5, 0, T-1)  — f32, uncontracted (HloEvaluator-folded)
__device__ __forceinline__ void pos_calc(int l, int &lo, int &hi, float &w) {
    const float SCALE = (float)(400.0 / 96000.0);
    float lf  = __fadd_rn((float)l, 0.5f);
    float pos = __fsub_rn(__fmul_rn(lf, SCALE), 0.5f);  // UNCONTRACTED
    pos = fminf(fmaxf(pos, 0.0f), 399.0f);
    float lof = floorf(pos);
    lo = (int)lof;
    hi = min(lo + 1, 399);
    w  = __fsub_rn(pos, lof);
}

// uncontracted lerp: add(mul, mul)
__device__ __forceinline__ float interp(float xlo, float xhi, float omw, float w) {
    return __fadd_rn(__fmul_rn(xlo, omw), __fmul_rn(xhi, w));
}

// fp32 leaf: inc = rn( rn(rn(2pi)*f0_up) / 24000 )   (R3 div form)
__device__ __forceinline__ float leaf_inc(const float* __restrict__ f0b, int l) {
    int lo, hi; float w;
    pos_calc(l, lo, hi, w);
    float omw = __fsub_rn(1.0f, w);
    float fv  = interp(f0b[lo], f0b[hi], omw, w);
    return __fdiv_rn(__fmul_rn(6.28318530717958648f, fv), 24000.0f);
}

// Accurate fp32 sin for |x| < 2^20, immune to --use_fast_math.
__device__ __forceinline__ float accurate_sinf(float x) {
    const float TWO_OVER_PI = 0.63661977236758134f;
    const float PIO2_HI     = 1.57079632679489662f;
    const float PIO2_MID    = -4.37113900018624283e-8f;
    float qx = __fmul_rn(x, TWO_OVER_PI);
    int   n  = __float2int_rn(qx);
    float q  = (float)n;
    float p  = __fmul_rn(q, PIO2_HI);
    float e  = __fmaf_rn(q, PIO2_HI, -p);
    float t  = __fsub_rn(x, p);
    float r  = __fsub_rn(t, e);
    r = __fsub_rn(r, __fmul_rn(q, PIO2_MID));
    float r2 = __fmul_rn(r, r);
    float ss = __fmaf_rn(r2, 2.7557319224e-6f, -1.9841269841e-4f);
    ss = __fmaf_rn(r2, ss, 8.3333333333e-3f);
    ss = __fmaf_rn(r2, ss, -1.6666666667e-1f);
    float sinr = __fmaf_rn(__fmul_rn(r, r2), ss, r);
    float cc = __fmaf_rn(r2, -2.7557319224e-7f, 2.4801587302e-5f);
    cc = __fmaf_rn(r2, cc, -1.3888888889e-3f);
    cc = __fmaf_rn(r2, cc, 4.1666666667e-2f);
    cc = __fmaf_rn(r2, cc, -0.5f);
    float cosr = __fmaf_rn(r2, cc, 1.0f);
    float s = (n & 1) ? cosr : sinr;
    return (n & 2) ? -s : s;
}

// ---------------- kernel 1: conv1 (128->32, k=3, pad=1) + leaky_relu(0.1) ----------------
__global__ void conv1_kernel(const float* __restrict__ cond,
                             const float* __restrict__ w1,
                             const float* __restrict__ b1) {
    int idx = blockIdx.x * blockDim.x + threadIdx.x;
    if (idx >= NB * 32 * TFRM) return;
    int t = idx % TFRM;
    int o = (idx / TFRM) % 32;
    int b = idx / (TFRM * 32);
    const float* xb = cond + b * 128 * TFRM;
    const float* wo = w1 + o * 128 * 3;
    float acc = b1[o];
    bool hasL = (t > 0), hasR = (t < TFRM - 1);
    #pragma unroll 4
    for (int i = 0; i < 128; i++) {
        const float* xp = xb + i * TFRM + t;
        float wa = wo[i*3], wb = wo[i*3+1], wc = wo[i*3+2];
        if (hasL) acc = __fmaf_rn(xp[-1], wa, acc);
        acc = __fmaf_rn(xp[0], wb, acc);
        if (hasR) acc = __fmaf_rn(xp[1], wc, acc);
    }
    g_h[idx] = (acc >= 0.0f) ? acc : __fmul_rn(0.1f, acc);
}

// ---------------- kernel 2: conv2 (32->1, k=3, pad=1) + sigmoid ----------------
__global__ void conv2_kernel(const float* __restrict__ w2,
                             const float* __restrict__ b2) {
    int idx = blockIdx.x * blockDim.x + threadIdx.x;
    if (idx >= NB * TFRM) return;
    int t = idx % TFRM;
    int b = idx / TFRM;
    float acc = b2[0];
    bool hasL = (t > 0), hasR = (t < TFRM - 1);
    #pragma unroll
    for (int i = 0; i < 32; i++) {
        const float* xp = g_h + (b * 32 + i) * TFRM + t;
        float wa = w2[i*3], wb = w2[i*3+1], wc = w2[i*3+2];
        if (hasL) acc = __fmaf_rn(xp[-1], wa, acc);
        acc = __fmaf_rn(xp[0], wb, acc);
        if (hasR) acc = __fmaf_rn(xp[1], wc, acc);
    }
    g_mix[idx] = 1.0f / (1.0f + expf(-acc));
}

// ---------------- kernel 3: XLA:CPU ReduceWindowRewriter scan, base_length = 16 ----------
// 96000 -> [6000,16] -> [375,16] -> pad 384 -> [24,16] -> pad 32 -> [2,16] -> serial-2.
// Inner windows: naive serial-ascending sums (equivalent to serial row prefix).
// Offsets: exclusive (previous row's inclusive total), applied with ONE rn-add per
// element per level. Padding zeros: add(x,0)=x bit-exact.
__global__ __launch_bounds__(1024) void scan_rwr16_kernel(const float* __restrict__ f0) {
    int b = blockIdx.x;
    const float* f0b = f0 + b * TFRM;
    float* ph = g_scan + b * LAUD;
    __shared__ float s1[6000];     // L1 values: first row totals, then in-place prefixes
    __shared__ float in2[384];     // L2 inner prefixes (padded)
    __shared__ float in3[32];      // L3 inner prefixes (padded)
    __shared__ float incl4[2];     // L4 inclusive
    int t = threadIdx.x;

    // L0: rows of 16 leaves, serial ascending; inner prefixes to ph, totals to s1
    for (int r = t; r < 6000; r += 1024) {
        int base = r * 16;
        float acc = 0.0f;
        #pragma unroll
        for (int j = 0; j < 16; j++) {
            acc = __fadd_rn(acc, leaf_inc(f0b, base + j));
            ph[base + j] = acc;
        }
        s1[r] = acc;
    }
    __syncthreads();

    // L1: [375,16] over s1, serial within row, in place (read-before-write ascending)
    for (int r = t; r < 375; r += 1024) {
        float acc = 0.0f;
        #pragma unroll
        for (int j = 0; j < 16; j++) {
            int idx = r * 16 + j;
            acc = __fadd_rn(acc, s1[idx]);
            s1[idx] = acc;
        }
    }
    __syncthreads();

    // L2: [24,16] over s2 (= s1[i*16+15]), pad 375->384 with zeros
    for (int r = t; r < 24; r += 1024) {
        float acc = 0.0f;
        #pragma unroll
        for (int j = 0; j < 16; j++) {
            int idx = r * 16 + j;               // index into s2 (0..383)
            float v = (idx < 375) ? s1[idx * 16 + 15] : 0.0f;
            acc = __fadd_rn(acc, v);
            in2[idx] = acc;
        }
    }
    __syncthreads();

    // L3: [2,16] over s3 (= in2[i*16+15]), pad 24->32 with zeros
    if (t < 2) {
        int r = t;
        float acc = 0.0f;
        #pragma unroll
        for (int j = 0; j < 16; j++) {
            int idx = r * 16 + j;               // index into s3 (0..31)
            float v = (idx < 24) ? in2[idx * 16 + 15] : 0.0f;
            acc = __fadd_rn(acc, v);
            in3[idx] = acc;
        }
    }
    __syncthreads();

    // L4: serial scan of 2 row totals
    if (t == 0) {
        incl4[0] = in3[15];
        incl4[1] = __fadd_rn(in3[15], in3[31]);
    }
    __syncthreads();

    // incl3: apply L4 offsets to in3 (rows of 16; row 0 offset is 0 -> exact)
    if (t < 32) {
        if (t >= 16) in3[t] = __fadd_rn(incl4[0], in3[t]);
    }
    __syncthreads();

    // incl2: apply incl3 offsets to in2
    for (int i = t; i < 384; i += 1024) {
        int r = i >> 4;
        if (r > 0) in2[i] = __fadd_rn(in3[r - 1], in2[i]);
    }
    __syncthreads();

    // incl1: apply incl2 offsets to s1
    for (int i = t; i < 6000; i += 1024) {
        int r = i >> 4;
        if (r > 0) s1[i] = __fadd_rn(in2[r - 1], s1[i]);
    }
    __syncthreads();

    // phase: apply incl1 offsets to inner0
    for (int l = t; l < LAUD; l += 1024) {
        int r = l >> 4;
        if (r > 0) ph[l] = __fadd_rn(s1[r - 1], ph[l]);
    }
}

// ---------------- kernel 4: harmonic synthesis + noise mix (R3 uncontracted forms) ----------------
__global__ __launch_bounds__(256) void synth_kernel(
        const float* __restrict__ amp, const float* __restrict__ off,
        const float* __restrict__ pat, const float* __restrict__ rst,
        const float* __restrict__ noise, float* __restrict__ out) {
    int tile = blockIdx.x % TFRM;
    int b    = blockIdx.x / TFRM;
    __shared__ float s_amp[3][NHARM], s_off[3][NHARM], s_pat[3][NHARM];
    int fbase = tile - 1;
    for (int idx = threadIdx.x; idx < 3 * NHARM; idx += blockDim.x) {
        int j = idx / NHARM, h = idx % NHARM;
        int fg = min(max(fbase + j, 0), TFRM - 1);
        int gi = (b * NHARM + h) * TFRM + fg;
        s_amp[j][h] = amp[gi];
        s_off[j][h] = off[gi];
        s_pat[j][h] = pat[gi];
    }
    __syncthreads();
    int tid = threadIdx.x;
    if (tid >= 240) return;
    int l = tile * 240 + tid;
    int lo, hi; float w;
    pos_calc(l, lo, hi, w);
    float omw = __fsub_rn(1.0f, w);
    float phase = g_scan[b * LAUD + l];
    float rv  = interp(rst[b * TFRM + lo], rst[b * TFRM + hi], omw, w);
    float omr = __fsub_rn(1.0f, rv);
    int flo = lo - fbase;
    int fhi = hi - fbase;
    float acc = 0.0f;
    float hm = 0.0f;
    #pragma unroll 4
    for (int h = 0; h < NHARM; h++) {
        hm = __fadd_rn(hm, 1.0f);
        float ov  = interp(s_off[flo][h], s_off[fhi][h], omw, w);
        float av  = interp(s_amp[flo][h], s_amp[fhi][h], omw, w);
        float pv  = interp(s_pat[flo][h], s_pat[fhi][h], omw, w);
        float bp  = __fmul_rn(phase, hm);
        float mod = __fadd_rn(bp, ov);
        float fin = __fadd_rn(__fmul_rn(mod, omr), __fmul_rn(pv, rv));
        acc = __fmaf_rn(accurate_sinf(fin), av, acc);
    }
    float mv  = interp(g_mix[b * TFRM + lo], g_mix[b * TFRM + hi], omw, w);
    float fm  = __fmul_rn(0.2f, mv);
    float nz  = noise[b * LAUD + l];
    out[b * LAUD + l] = __fadd_rn(__fmul_rn(__fsub_rn(1.0f, fm), acc),
                                  __fmul_rn(fm, nz));
}

// ---------------- launch ----------------
extern "C" void kernel_launch(void* const* d_in, const int* in_sizes, int n_in,
                              void* d_out, int out_size) {
    const float* f0    = (const float*)d_in[0];
    const float* cond  = (const float*)d_in[1];
    const float* amp   = (const float*)d_in[2];
    const float* offp  = (const float*)d_in[3];
    const float* rst   = (const float*)d_in[4];
    const float* pat   = (const float*)d_in[5];
    const float* noise = (const float*)d_in[6];
    const float* w1    = (const float*)d_in[7];
    const float* b1    = (const float*)d_in[8];
    const float* w2    = (const float*)d_in[9];
    const float* b2    = (const float*)d_in[10];
    float* out = (float*)d_out;

    conv1_kernel<<<(NB*32*TFRM + 255)/256, 256>>>(cond, w1, b1);
    conv2_kernel<<<(NB*TFRM + 255)/256, 256>>>(w2, b2);
    scan_rwr16_kernel<<<NB, 1024>>>(f0);
    synth_kernel<<<NB*TFRM, 256>>>(amp, offp, pat, rst, noise, out);
}

// round 16
// speedup vs baseline: 1.6470x; 1.6470x over previous
#include <cuda_runtime.h>
#include <cuda_bf16.h>

// ---------------- problem constants ----------------
#define NB     4
#define TFRM   400
#define NHARM  100
#define LAUD   96000
#define NROWS  6000        // L0 rows of 16

typedef unsigned long long ull;

// ---------------- static device scratch ----------------
__device__ float g_scan[NB * LAUD];   // L0 inner prefixes (row-local)
__device__ float g_s1[NB * NROWS];    // row totals -> then incl1 offsets
__device__ float g_h[NB * 32 * TFRM]; // conv1 activations
__device__ float g_mix[NB * TFRM];    // sigmoid mix at frame rate

// ---------------- f32x2 packed helpers (used ONLY on value-level math) ----------------
__device__ __forceinline__ ull pk2(float lo, float hi) {
    ull r; asm("mov.b64 %0, {%1, %2};" : "=l"(r) : "f"(lo), "f"(hi)); return r;
}
__device__ __forceinline__ void unpk2(ull v, float &lo, float &hi) {
    asm("mov.b64 {%0, %1}, %2;" : "=f"(lo), "=f"(hi) : "l"(v));
}
__device__ __forceinline__ ull mul2(ull a, ull b) {
    ull r; asm("mul.rn.f32x2 %0, %1, %2;" : "=l"(r) : "l"(a), "l"(b)); return r;
}
__device__ __forceinline__ ull add2(ull a, ull b) {
    ull r; asm("add.rn.f32x2 %0, %1, %2;" : "=l"(r) : "l"(a), "l"(b)); return r;
}
__device__ __forceinline__ ull fma2(ull a, ull b, ull c) {
    ull r; asm("fma.rn.f32x2 %0, %1, %2, %3;" : "=l"(r) : "l"(a), "l"(b), "l"(c)); return r;
}
__device__ __forceinline__ ull dup2(float x) { return pk2(x, x); }

// ---------------- rounding-exact helpers (R14 forms, all uncontracted) ----------------

__device__ __forceinline__ void pos_calc(int l, int &lo, int &hi, float &w) {
    const float SCALE = (float)(400.0 / 96000.0);
    float lf  = __fadd_rn((float)l, 0.5f);
    float pos = __fsub_rn(__fmul_rn(lf, SCALE), 0.5f);  // UNCONTRACTED
    pos = fminf(fmaxf(pos, 0.0f), 399.0f);
    float lof = floorf(pos);
    lo = (int)lof;
    hi = min(lo + 1, 399);
    w  = __fsub_rn(pos, lof);
}

__device__ __forceinline__ float interp(float xlo, float xhi, float omw, float w) {
    return __fadd_rn(__fmul_rn(xlo, omw), __fmul_rn(xhi, w));
}

__device__ __forceinline__ float leaf_inc(const float* __restrict__ f0b, int l) {
    int lo, hi; float w;
    pos_calc(l, lo, hi, w);
    float omw = __fsub_rn(1.0f, w);
    float fv  = interp(f0b[lo], f0b[hi], omw, w);
    return __fdiv_rn(__fmul_rn(6.28318530717958648f, fv), 24000.0f);
}

// ---------------- kernel 1: conv1 (128->32, k=3, pad=1) + leaky_relu(0.1) ----------------
__global__ void conv1_kernel(const float* __restrict__ cond,
                             const float* __restrict__ w1,
                             const float* __restrict__ b1) {
    int idx = blockIdx.x * blockDim.x + threadIdx.x;
    if (idx >= NB * 32 * TFRM) return;
    int t = idx % TFRM;
    int o = (idx / TFRM) % 32;
    int b = idx / (TFRM * 32);
    const float* xb = cond + b * 128 * TFRM;
    const float* wo = w1 + o * 128 * 3;
    float acc = b1[o];
    bool hasL = (t > 0), hasR = (t < TFRM - 1);
    #pragma unroll 4
    for (int i = 0; i < 128; i++) {
        const float* xp = xb + i * TFRM + t;
        float wa = wo[i*3], wb = wo[i*3+1], wc = wo[i*3+2];
        if (hasL) acc = __fmaf_rn(xp[-1], wa, acc);
        acc = __fmaf_rn(xp[0], wb, acc);
        if (hasR) acc = __fmaf_rn(xp[1], wc, acc);
    }
    g_h[idx] = (acc >= 0.0f) ? acc : __fmul_rn(0.1f, acc);
}

// ---------------- kernel 2: conv2 (32->1, k=3, pad=1) + sigmoid ----------------
__global__ void conv2_kernel(const float* __restrict__ w2,
                             const float* __restrict__ b2) {
    int idx = blockIdx.x * blockDim.x + threadIdx.x;
    if (idx >= NB * TFRM) return;
    int t = idx % TFRM;
    int b = idx / TFRM;
    float acc = b2[0];
    bool hasL = (t > 0), hasR = (t < TFRM - 1);
    #pragma unroll
    for (int i = 0; i < 32; i++) {
        const float* xp = g_h + (b * 32 + i) * TFRM + t;
        float wa = w2[i*3], wb = w2[i*3+1], wc = w2[i*3+2];
        if (hasL) acc = __fmaf_rn(xp[-1], wa, acc);
        acc = __fmaf_rn(xp[0], wb, acc);
        if (hasR) acc = __fmaf_rn(xp[1], wc, acc);
    }
    g_mix[idx] = 1.0f / (1.0f + expf(-acc));
}

// ---------------- kernel 3a: L0 rows (full-chip parallel, scalar, bit-identical R14) ----------
__global__ __launch_bounds__(256) void scan_rows_kernel(const float* __restrict__ f0) {
    int rid = blockIdx.x * blockDim.x + threadIdx.x;
    if (rid >= NB * NROWS) return;
    int b = rid / NROWS;
    int r = rid % NROWS;
    const float* f0b = f0 + b * TFRM;
    float* ph = g_scan + b * LAUD;
    int base = r * 16;
    float acc = 0.0f;
    #pragma unroll
    for (int j = 0; j < 16; j++) {
        acc = __fadd_rn(acc, leaf_inc(f0b, base + j));
        ph[base + j] = acc;
    }
    g_s1[b * NROWS + r] = acc;
}

// ---------------- kernel 3b: upper levels L1..L4 (scalar, bit-identical R14) ----------
__global__ __launch_bounds__(512) void scan_levels_kernel() {
    int b = blockIdx.x;
    __shared__ float s1[NROWS];
    __shared__ float in2[384];
    __shared__ float in3[32];
    __shared__ float incl4[2];
    int t = threadIdx.x;

    for (int i = t; i < NROWS; i += 512) s1[i] = g_s1[b * NROWS + i];
    __syncthreads();

    if (t < 375) {
        float acc = 0.0f;
        #pragma unroll
        for (int j = 0; j < 16; j++) {
            int idx = t * 16 + j;
            acc = __fadd_rn(acc, s1[idx]);
            s1[idx] = acc;
        }
    }
    __syncthreads();

    if (t < 24) {
        float acc = 0.0f;
        #pragma unroll
        for (int j = 0; j < 16; j++) {
            int idx = t * 16 + j;
            float v = (idx < 375) ? s1[idx * 16 + 15] : 0.0f;
            acc = __fadd_rn(acc, v);
            in2[idx] = acc;
        }
    }
    __syncthreads();

    if (t < 2) {
        float acc = 0.0f;
        #pragma unroll
        for (int j = 0; j < 16; j++) {
            int idx = t * 16 + j;
            float v = (idx < 24) ? in2[idx * 16 + 15] : 0.0f;
            acc = __fadd_rn(acc, v);
            in3[idx] = acc;
        }
    }
    __syncthreads();

    if (t == 0) {
        incl4[0] = in3[15];
        incl4[1] = __fadd_rn(in3[15], in3[31]);
    }
    __syncthreads();

    if (t >= 16 && t < 32) in3[t] = __fadd_rn(incl4[0], in3[t]);
    __syncthreads();

    if (t < 384) {
        int r = t >> 4;
        if (r > 0) in2[t] = __fadd_rn(in3[r - 1], in2[t]);
    }
    __syncthreads();

    for (int i = t; i < NROWS; i += 512) {
        int r = i >> 4;
        float v = (r > 0) ? __fadd_rn(in2[r - 1], s1[i]) : s1[i];
        g_s1[b * NROWS + i] = v;
    }
}

// ---------------- kernel 4: harmonic synthesis + noise mix ----------------
// CRITICAL chain (bp/mod/fin) in exact R14 scalar ops; value-level math
// (interpolations, sin reduction+poly) packed f32x2 — robust to <=1-ulp
// deviations in the packed instructions.
__global__ __launch_bounds__(256) void synth_kernel(
        const float* __restrict__ amp, const float* __restrict__ off,
        const float* __restrict__ pat, const float* __restrict__ rst,
        const float* __restrict__ noise, float* __restrict__ out) {
    int tile = blockIdx.x % TFRM;
    int b    = blockIdx.x / TFRM;
    __shared__ __align__(8) float s_amp[3][NHARM];
    __shared__ __align__(8) float s_off[3][NHARM];
    __shared__ __align__(8) float s_pat[3][NHARM];
    int fbase = tile - 1;
    for (int idx = threadIdx.x; idx < 3 * NHARM; idx += blockDim.x) {
        int j = idx / NHARM, h = idx % NHARM;
        int fg = min(max(fbase + j, 0), TFRM - 1);
        int gi = (b * NHARM + h) * TFRM + fg;
        s_amp[j][h] = amp[gi];
        s_off[j][h] = off[gi];
        s_pat[j][h] = pat[gi];
    }
    __syncthreads();
    int tid = threadIdx.x;
    if (tid >= 240) return;
    int l = tile * 240 + tid;
    int lo, hi; float w;
    pos_calc(l, lo, hi, w);
    float omw = __fsub_rn(1.0f, w);
    // fused phase offset (same scalar __fadd_rn as R14's scan epilogue)
    int r = l >> 4;
    float inner = g_scan[b * LAUD + l];
    float phase = (r > 0) ? __fadd_rn(g_s1[b * NROWS + r - 1], inner) : inner;
    float rv  = interp(rst[b * TFRM + lo], rst[b * TFRM + hi], omw, w);
    float omr = __fsub_rn(1.0f, rv);
    int flo = lo - fbase;
    int fhi = hi - fbase;

    // packed constants (value-level paths only)
    const ull W2    = dup2(w);
    const ull OMW2  = dup2(omw);
    const ull TOPI2 = dup2(0.63661977236758134f);
    const ull PIHI2 = dup2(1.57079632679489662f);
    const ull NMID2 = dup2(4.37113900018624283e-8f);   // -(PIO2_MID)
    const ull NEG12 = dup2(-1.0f);
    const ull ONE2  = dup2(1.0f);
    const ull S4 = dup2(2.7557319224e-6f),  S3 = dup2(-1.9841269841e-4f);
    const ull S2 = dup2(8.3333333333e-3f),  S1 = dup2(-1.6666666667e-1f);
    const ull C5 = dup2(-2.7557319224e-7f), C4 = dup2(2.4801587302e-5f);
    const ull C3 = dup2(-1.3888888889e-3f), C2 = dup2(4.1666666667e-2f);
    const ull C1 = dup2(-0.5f);

    float hm0 = 1.0f, hm1 = 2.0f;        // exact integers, step 2
    float acc0 = 0.0f, acc1 = 0.0f;

    const float* offlo = s_off[flo]; const float* offhi = s_off[fhi];
    const float* amplo = s_amp[flo]; const float* amphi = s_amp[fhi];
    const float* patlo = s_pat[flo]; const float* pathi = s_pat[fhi];

    #pragma unroll 2
    for (int h = 0; h < NHARM; h += 2) {
        ull olo = *(const ull*)(offlo + h), ohi = *(const ull*)(offhi + h);
        ull alo = *(const ull*)(amplo + h), ahi = *(const ull*)(amphi + h);
        ull plo = *(const ull*)(patlo + h), phi = *(const ull*)(pathi + h);
        // value-level interps (packed; <=1-ulp deviation harmless: 6e-9 << ulp(fin))
        ull ov2 = add2(mul2(olo, OMW2), mul2(ohi, W2));
        ull av2 = add2(mul2(alo, OMW2), mul2(ahi, W2));
        ull pv2 = add2(mul2(plo, OMW2), mul2(phi, W2));
        float ov0, ov1, pv0, pv1, av0, av1;
        unpk2(ov2, ov0, ov1);
        unpk2(pv2, pv0, pv1);
        unpk2(av2, av0, av1);
        // CRITICAL chain — exact R14 scalar rounding
        float bp0  = __fmul_rn(phase, hm0);
        float mod0 = __fadd_rn(bp0, ov0);
        float fin0 = __fadd_rn(__fmul_rn(mod0, omr), __fmul_rn(pv0, rv));
        float bp1  = __fmul_rn(phase, hm1);
        float mod1 = __fadd_rn(bp1, ov1);
        float fin1 = __fadd_rn(__fmul_rn(mod1, omr), __fmul_rn(pv1, rv));
        ull fin2 = pk2(fin0, fin1);
        // packed sin (value-level; reduction exact under any per-lane rounding)
        ull qx2 = mul2(fin2, TOPI2);
        float qx0, qx1; unpk2(qx2, qx0, qx1);
        int n0 = __float2int_rn(qx0), n1 = __float2int_rn(qx1);
        ull q2  = pk2((float)n0, (float)n1);
        ull p2  = mul2(q2, PIHI2);
        ull np2 = mul2(p2, NEG12);                         // exact negation
        ull e2  = fma2(q2, PIHI2, np2);                    // exact two-product residual
        ull t2  = add2(fin2, np2);                         // Sterbenz-exact
        ull r2v = fma2(e2, NEG12, t2);
        r2v = add2(r2v, mul2(q2, NMID2));
        ull rsq = mul2(r2v, r2v);
        ull ss = fma2(rsq, S4, S3);
        ss = fma2(rsq, ss, S2);
        ss = fma2(rsq, ss, S1);
        ull sin2v = fma2(mul2(r2v, rsq), ss, r2v);
        ull cc = fma2(rsq, C5, C4);
        cc = fma2(rsq, cc, C3);
        cc = fma2(rsq, cc, C2);
        cc = fma2(rsq, cc, C1);
        ull cos2v = fma2(rsq, cc, ONE2);
        float si0, si1, co0, co1;
        unpk2(sin2v, si0, si1);
        unpk2(cos2v, co0, co1);
        float r0 = (n0 & 1) ? co0 : si0;
        r0 = __int_as_float(__float_as_int(r0) ^ ((n0 & 2) << 30));
        acc0 = __fmaf_rn(r0, av0, acc0);
        float r1 = (n1 & 1) ? co1 : si1;
        r1 = __int_as_float(__float_as_int(r1) ^ ((n1 & 2) << 30));
        acc1 = __fmaf_rn(r1, av1, acc1);
        hm0 = __fadd_rn(hm0, 2.0f);                        // exact
        hm1 = __fadd_rn(hm1, 2.0f);
    }
    float acc = __fadd_rn(acc0, acc1);                     // value-level reorder only

    float mv  = interp(g_mix[b * TFRM + lo], g_mix[b * TFRM + hi], omw, w);
    float fm  = __fmul_rn(0.2f, mv);
    float nz  = noise[b * LAUD + l];
    out[b * LAUD + l] = __fadd_rn(__fmul_rn(__fsub_rn(1.0f, fm), acc),
                                  __fmul_rn(fm, nz));
}

// ---------------- launch ----------------
extern "C" void kernel_launch(void* const* d_in, const int* in_sizes, int n_in,
                              void* d_out, int out_size) {
    const float* f0    = (const float*)d_in[0];
    const float* cond  = (const float*)d_in[1];
    const float* amp   = (const float*)d_in[2];
    const float* offp  = (const float*)d_in[3];
    const float* rst   = (const float*)d_in[4];
    const float* pat   = (const float*)d_in[5];
    const float* noise = (const float*)d_in[6];
    const float* w1    = (const float*)d_in[7];
    const float* b1    = (const float*)d_in[8];
    const float* w2    = (const float*)d_in[9];
    const float* b2    = (const float*)d_in[10];
    float* out = (float*)d_out;

    scan_rows_kernel<<<(NB*NROWS + 255)/256, 256>>>(f0);
    conv1_kernel<<<(NB*32*TFRM + 255)/256, 256>>>(cond, w1, b1);
    conv2_kernel<<<(NB*TFRM + 255)/256, 256>>>(w2, b2);
    scan_levels_kernel<<<NB, 512>>>();
    synth_kernel<<<NB*TFRM, 256>>>(amp, offp, pat, rst, noise, out);
}

// round 17
// speedup vs baseline: 1.7217x; 1.0453x over previous
#include <cuda_runtime.h>
#include <cuda_bf16.h>

// ---------------- problem constants ----------------
#define NB     4
#define TFRM   400
#define NHARM  100
#define LAUD   96000
#define NROWS  6000        // L0 rows of 16

typedef unsigned long long ull;

// ---------------- static device scratch ----------------
__device__ float g_scan[NB * LAUD];   // L0 inner prefixes (row-local)
__device__ float g_s1[NB * NROWS];    // row totals -> L1-scanned (incl2 offsets NOT applied)
__device__ float g_in2[NB * 384];     // incl2 (L2 inner prefixes with L3/L4 offsets applied)
__device__ float g_h[NB * 32 * TFRM]; // conv1 activations
__device__ float g_mix[NB * TFRM];    // sigmoid mix at frame rate

// ---------------- f32x2 packed helpers (value-level math only) ----------------
__device__ __forceinline__ ull pk2(float lo, float hi) {
    ull r; asm("mov.b64 %0, {%1, %2};" : "=l"(r) : "f"(lo), "f"(hi)); return r;
}
__device__ __forceinline__ void unpk2(ull v, float &lo, float &hi) {
    asm("mov.b64 {%0, %1}, %2;" : "=f"(lo), "=f"(hi) : "l"(v));
}
__device__ __forceinline__ ull mul2(ull a, ull b) {
    ull r; asm("mul.rn.f32x2 %0, %1, %2;" : "=l"(r) : "l"(a), "l"(b)); return r;
}
__device__ __forceinline__ ull add2(ull a, ull b) {
    ull r; asm("add.rn.f32x2 %0, %1, %2;" : "=l"(r) : "l"(a), "l"(b)); return r;
}
__device__ __forceinline__ ull fma2(ull a, ull b, ull c) {
    ull r; asm("fma.rn.f32x2 %0, %1, %2, %3;" : "=l"(r) : "l"(a), "l"(b), "l"(c)); return r;
}
__device__ __forceinline__ ull dup2(float x) { return pk2(x, x); }

// ---------------- rounding-exact helpers (R14 forms, all uncontracted) ----------------

__device__ __forceinline__ void pos_calc(int l, int &lo, int &hi, float &w) {
    const float SCALE = (float)(400.0 / 96000.0);
    float lf  = __fadd_rn((float)l, 0.5f);
    float pos = __fsub_rn(__fmul_rn(lf, SCALE), 0.5f);  // UNCONTRACTED
    pos = fminf(fmaxf(pos, 0.0f), 399.0f);
    float lof = floorf(pos);
    lo = (int)lof;
    hi = min(lo + 1, 399);
    w  = __fsub_rn(pos, lof);
}

__device__ __forceinline__ float interp(float xlo, float xhi, float omw, float w) {
    return __fadd_rn(__fmul_rn(xlo, omw), __fmul_rn(xhi, w));
}

__device__ __forceinline__ float leaf_inc(const float* __restrict__ f0b, int l) {
    int lo, hi; float w;
    pos_calc(l, lo, hi, w);
    float omw = __fsub_rn(1.0f, w);
    float fv  = interp(f0b[lo], f0b[hi], omw, w);
    return __fdiv_rn(__fmul_rn(6.28318530717958648f, fv), 24000.0f);
}

// ---------------- kernel 1: conv1 (128->32, k=3, pad=1) + leaky_relu(0.1) ----------------
__global__ void conv1_kernel(const float* __restrict__ cond,
                             const float* __restrict__ w1,
                             const float* __restrict__ b1) {
    int idx = blockIdx.x * blockDim.x + threadIdx.x;
    if (idx >= NB * 32 * TFRM) return;
    int t = idx % TFRM;
    int o = (idx / TFRM) % 32;
    int b = idx / (TFRM * 32);
    const float* xb = cond + b * 128 * TFRM;
    const float* wo = w1 + o * 128 * 3;
    float acc = b1[o];
    bool hasL = (t > 0), hasR = (t < TFRM - 1);
    #pragma unroll 4
    for (int i = 0; i < 128; i++) {
        const float* xp = xb + i * TFRM + t;
        float wa = wo[i*3], wb = wo[i*3+1], wc = wo[i*3+2];
        if (hasL) acc = __fmaf_rn(xp[-1], wa, acc);
        acc = __fmaf_rn(xp[0], wb, acc);
        if (hasR) acc = __fmaf_rn(xp[1], wc, acc);
    }
    g_h[idx] = (acc >= 0.0f) ? acc : __fmul_rn(0.1f, acc);
}

// ---------------- kernel 2: conv2 (32->1, k=3, pad=1) + sigmoid ----------------
__global__ void conv2_kernel(const float* __restrict__ w2,
                             const float* __restrict__ b2) {
    int idx = blockIdx.x * blockDim.x + threadIdx.x;
    if (idx >= NB * TFRM) return;
    int t = idx % TFRM;
    int b = idx / TFRM;
    float acc = b2[0];
    bool hasL = (t > 0), hasR = (t < TFRM - 1);
    #pragma unroll
    for (int i = 0; i < 32; i++) {
        const float* xp = g_h + (b * 32 + i) * TFRM + t;
        float wa = w2[i*3], wb = w2[i*3+1], wc = w2[i*3+2];
        if (hasL) acc = __fmaf_rn(xp[-1], wa, acc);
        acc = __fmaf_rn(xp[0], wb, acc);
        if (hasR) acc = __fmaf_rn(xp[1], wc, acc);
    }
    g_mix[idx] = 1.0f / (1.0f + expf(-acc));
}

// ---------------- kernel 3a: L0 rows (full-chip parallel, scalar, bit-identical R14) ----------
__global__ __launch_bounds__(256) void scan_rows_kernel(const float* __restrict__ f0) {
    int rid = blockIdx.x * blockDim.x + threadIdx.x;
    if (rid >= NB * NROWS) return;
    int b = rid / NROWS;
    int r = rid % NROWS;
    const float* f0b = f0 + b * TFRM;
    float* ph = g_scan + b * LAUD;
    int base = r * 16;
    float acc = 0.0f;
    #pragma unroll
    for (int j = 0; j < 16; j++) {
        acc = __fadd_rn(acc, leaf_inc(f0b, base + j));
        ph[base + j] = acc;
    }
    g_s1[b * NROWS + r] = acc;
}

// ---------------- kernel 3b: upper levels (vectorized; incl1-apply moved into synth) --------
// L1: [375,16] serial scan in REGISTERS (same fp ops/order as R14's in-place smem walk).
// L2: [24,16]; L3: [2,16]; L4: serial-2; incl3 -> in2 offsets applied; write s1-scanned + in2.
__global__ __launch_bounds__(512) void scan_levels_kernel() {
    int b = blockIdx.x;
    __shared__ __align__(16) float s1[NROWS];
    __shared__ float in2[384];
    __shared__ float in3[32];
    __shared__ float incl4[2];
    int t = threadIdx.x;

    const float4* src = (const float4*)(g_s1 + b * NROWS);
    float4* s1v4 = (float4*)s1;
    for (int i = t; i < NROWS / 4; i += 512) s1v4[i] = src[i];
    __syncthreads();

    // L1: register-resident serial-16 scan (add(+0,x)=x exact; positive values)
    if (t < 375) {
        float4 a = s1v4[t*4+0], bb = s1v4[t*4+1], c = s1v4[t*4+2], d = s1v4[t*4+3];
        float x0=a.x,  x1=a.y,  x2=a.z,  x3=a.w;
        float x4=bb.x, x5=bb.y, x6=bb.z, x7=bb.w;
        float x8=c.x,  x9=c.y,  x10=c.z, x11=c.w;
        float x12=d.x, x13=d.y, x14=d.z, x15=d.w;
        x1  = __fadd_rn(x0,  x1);  x2  = __fadd_rn(x1,  x2);  x3  = __fadd_rn(x2,  x3);
        x4  = __fadd_rn(x3,  x4);  x5  = __fadd_rn(x4,  x5);  x6  = __fadd_rn(x5,  x6);
        x7  = __fadd_rn(x6,  x7);  x8  = __fadd_rn(x7,  x8);  x9  = __fadd_rn(x8,  x9);
        x10 = __fadd_rn(x9,  x10); x11 = __fadd_rn(x10, x11); x12 = __fadd_rn(x11, x12);
        x13 = __fadd_rn(x12, x13); x14 = __fadd_rn(x13, x14); x15 = __fadd_rn(x14, x15);
        s1v4[t*4+0] = make_float4(x0,  x1,  x2,  x3);
        s1v4[t*4+1] = make_float4(x4,  x5,  x6,  x7);
        s1v4[t*4+2] = make_float4(x8,  x9,  x10, x11);
        s1v4[t*4+3] = make_float4(x12, x13, x14, x15);
    }
    __syncthreads();

    // L2: [24,16] over s2 (= s1[idx*16+15]), pad 375->384 with zeros
    if (t < 24) {
        float acc = 0.0f;
        #pragma unroll
        for (int j = 0; j < 16; j++) {
            int idx = t * 16 + j;
            float v = (idx < 375) ? s1[idx * 16 + 15] : 0.0f;
            acc = __fadd_rn(acc, v);
            in2[idx] = acc;
        }
    }
    __syncthreads();

    // L3: [2,16] over s3 (= in2[i*16+15]), pad 24->32 with zeros
    if (t < 2) {
        float acc = 0.0f;
        #pragma unroll
        for (int j = 0; j < 16; j++) {
            int idx = t * 16 + j;
            float v = (idx < 24) ? in2[idx * 16 + 15] : 0.0f;
            acc = __fadd_rn(acc, v);
            in3[idx] = acc;
        }
    }
    __syncthreads();

    // L4: serial scan of 2
    if (t == 0) {
        incl4[0] = in3[15];
        incl4[1] = __fadd_rn(in3[15], in3[31]);
    }
    __syncthreads();

    // incl3
    if (t >= 16 && t < 32) in3[t] = __fadd_rn(incl4[0], in3[t]);
    __syncthreads();

    // incl2: apply incl3 offsets; write to global
    if (t < 384) {
        int r = t >> 4;
        float v = (r > 0) ? __fadd_rn(in3[r - 1], in2[t]) : in2[t];
        g_in2[b * 384 + t] = v;
    }

    // write back L1-scanned s1 (incl2 offsets applied later in synth — same ops/order)
    float4* dst = (float4*)(g_s1 + b * NROWS);
    for (int i = t; i < NROWS / 4; i += 512) dst[i] = s1v4[i];
}

// ---------------- kernel 4: harmonic synthesis + noise mix ----------------
// CRITICAL chain (bp/mod/mod*omr/fin-add + phase offset adds) scalar R14 ops;
// value-level math (interps, pv*rv, sin reduction+poly) packed f32x2.
__global__ __launch_bounds__(256) void synth_kernel(
        const float* __restrict__ amp, const float* __restrict__ off,
        const float* __restrict__ pat, const float* __restrict__ rst,
        const float* __restrict__ noise, float* __restrict__ out) {
    int tile = blockIdx.x % TFRM;
    int b    = blockIdx.x / TFRM;
    __shared__ __align__(8) float s_amp[3][NHARM];
    __shared__ __align__(8) float s_off[3][NHARM];
    __shared__ __align__(8) float s_pat[3][NHARM];
    int fbase = tile - 1;
    for (int idx = threadIdx.x; idx < 3 * NHARM; idx += blockDim.x) {
        int j = idx / NHARM, h = idx % NHARM;
        int fg = min(max(fbase + j, 0), TFRM - 1);
        int gi = (b * NHARM + h) * TFRM + fg;
        s_amp[j][h] = amp[gi];
        s_off[j][h] = off[gi];
        s_pat[j][h] = pat[gi];
    }
    __syncthreads();
    int tid = threadIdx.x;
    if (tid >= 240) return;
    int l = tile * 240 + tid;
    int lo, hi; float w;
    pos_calc(l, lo, hi, w);
    float omw = __fsub_rn(1.0f, w);
    // phase = add(incl1[r-1], inner);  incl1[r-1] = add(in2[r1-1], s1[r-1])
    // (identical scalar ops/order as R16's scan epilogue + fused add)
    int r = l >> 4;
    float inner = g_scan[b * LAUD + l];
    float phase;
    if (r > 0) {
        int i  = r - 1;
        int r1 = i >> 4;
        float s1v = g_s1[b * NROWS + i];
        float offv = (r1 > 0) ? __fadd_rn(g_in2[b * 384 + r1 - 1], s1v) : s1v;
        phase = __fadd_rn(offv, inner);
    } else {
        phase = inner;
    }
    float rv  = interp(rst[b * TFRM + lo], rst[b * TFRM + hi], omw, w);
    float omr = __fsub_rn(1.0f, rv);
    int flo = lo - fbase;
    int fhi = hi - fbase;

    // packed constants (value-level paths only)
    const ull W2    = dup2(w);
    const ull OMW2  = dup2(omw);
    const ull RV2   = dup2(rv);
    const ull TOPI2 = dup2(0.63661977236758134f);
    const ull PIHI2 = dup2(1.57079632679489662f);
    const ull NMID2 = dup2(4.37113900018624283e-8f);   // -(PIO2_MID)
    const ull NEG12 = dup2(-1.0f);
    const ull ONE2  = dup2(1.0f);
    const ull S4 = dup2(2.7557319224e-6f),  S3 = dup2(-1.9841269841e-4f);
    const ull S2 = dup2(8.3333333333e-3f),  S1 = dup2(-1.6666666667e-1f);
    const ull C5 = dup2(-2.7557319224e-7f), C4 = dup2(2.4801587302e-5f);
    const ull C3 = dup2(-1.3888888889e-3f), C2 = dup2(4.1666666667e-2f);
    const ull C1 = dup2(-0.5f);

    float hm0 = 1.0f, hm1 = 2.0f;        // exact integers, step 2
    float acc0 = 0.0f, acc1 = 0.0f;

    const float* offlo = s_off[flo]; const float* offhi = s_off[fhi];
    const float* amplo = s_amp[flo]; const float* amphi = s_amp[fhi];
    const float* patlo = s_pat[flo]; const float* pathi = s_pat[fhi];

    #pragma unroll 2
    for (int h = 0; h < NHARM; h += 2) {
        ull olo = *(const ull*)(offlo + h), ohi = *(const ull*)(offhi + h);
        ull alo = *(const ull*)(amplo + h), ahi = *(const ull*)(amphi + h);
        ull plo = *(const ull*)(patlo + h), phi = *(const ull*)(pathi + h);
        ull ov2 = add2(mul2(olo, OMW2), mul2(ohi, W2));
        ull av2 = add2(mul2(alo, OMW2), mul2(ahi, W2));
        ull pv2 = add2(mul2(plo, OMW2), mul2(phi, W2));
        ull pr2 = mul2(pv2, RV2);                          // value-level product
        float ov0, ov1, pr0, pr1, av0, av1;
        unpk2(ov2, ov0, ov1);
        unpk2(pr2, pr0, pr1);
        unpk2(av2, av0, av1);
        // CRITICAL chain — exact R14 scalar rounding
        float bp0  = __fmul_rn(phase, hm0);
        float mod0 = __fadd_rn(bp0, ov0);
        float fin0 = __fadd_rn(__fmul_rn(mod0, omr), pr0);
        float bp1  = __fmul_rn(phase, hm1);
        float mod1 = __fadd_rn(bp1, ov1);
        float fin1 = __fadd_rn(__fmul_rn(mod1, omr), pr1);
        ull fin2 = pk2(fin0, fin1);
        // packed sin (value-level; reduction exact under per-lane rn)
        ull qx2 = mul2(fin2, TOPI2);
        float qx0, qx1; unpk2(qx2, qx0, qx1);
        int n0 = __float2int_rn(qx0), n1 = __float2int_rn(qx1);
        ull q2  = pk2((float)n0, (float)n1);
        ull p2  = mul2(q2, PIHI2);
        ull np2 = mul2(p2, NEG12);                         // exact negation
        ull e2  = fma2(q2, PIHI2, np2);                    // exact two-product residual
        ull t2  = add2(fin2, np2);                         // Sterbenz-exact
        ull r2v = fma2(e2, NEG12, t2);
        r2v = add2(r2v, mul2(q2, NMID2));
        ull rsq = mul2(r2v, r2v);
        ull ss = fma2(rsq, S4, S3);
        ss = fma2(rsq, ss, S2);
        ss = fma2(rsq, ss, S1);
        ull sin2v = fma2(mul2(r2v, rsq), ss, r2v);
        ull cc = fma2(rsq, C5, C4);
        cc = fma2(rsq, cc, C3);
        cc = fma2(rsq, cc, C2);
        cc = fma2(rsq, cc, C1);
        ull cos2v = fma2(rsq, cc, ONE2);
        float si0, si1, co0, co1;
        unpk2(sin2v, si0, si1);
        unpk2(cos2v, co0, co1);
        float r0 = (n0 & 1) ? co0 : si0;
        r0 = __int_as_float(__float_as_int(r0) ^ ((n0 & 2) << 30));
        acc0 = __fmaf_rn(r0, av0, acc0);
        float r1 = (n1 & 1) ? co1 : si1;
        r1 = __int_as_float(__float_as_int(r1) ^ ((n1 & 2) << 30));
        acc1 = __fmaf_rn(r1, av1, acc1);
        hm0 = __fadd_rn(hm0, 2.0f);
        hm1 = __fadd_rn(hm1, 2.0f);
    }
    float acc = __fadd_rn(acc0, acc1);

    float mv  = interp(g_mix[b * TFRM + lo], g_mix[b * TFRM + hi], omw, w);
    float fm  = __fmul_rn(0.2f, mv);
    float nz  = noise[b * LAUD + l];
    out[b * LAUD + l] = __fadd_rn(__fmul_rn(__fsub_rn(1.0f, fm), acc),
                                  __fmul_rn(fm, nz));
}

// ---------------- launch ----------------
extern "C" void kernel_launch(void* const* d_in, const int* in_sizes, int n_in,
                              void* d_out, int out_size) {
    const float* f0    = (const float*)d_in[0];
    const float* cond  = (const float*)d_in[1];
    const float* amp   = (const float*)d_in[2];
    const float* offp  = (const float*)d_in[3];
    const float* rst   = (const float*)d_in[4];
    const float* pat   = (const float*)d_in[5];
    const float* noise = (const float*)d_in[6];
    const float* w1    = (const float*)d_in[7];
    const float* b1    = (const float*)d_in[8];
    const float* w2    = (const float*)d_in[9];
    const float* b2    = (const float*)d_in[10];
    float* out = (float*)d_out;

    scan_rows_kernel<<<(NB*NROWS + 255)/256, 256>>>(f0);
    conv1_kernel<<<(NB*32*TFRM + 255)/256, 256>>>(cond, w1, b1);
    conv2_kernel<<<(NB*TFRM + 255)/256, 256>>>(w2, b2);
    scan_levels_kernel<<<NB, 512>>>();
    synth_kernel<<<NB*TFRM, 256>>>(amp, offp, pat, rst, noise, out);
}